// round 8
// baseline (speedup 1.0000x reference)
#include <cuda_runtime.h>

// QuantumImagePreprocessor: Heisenberg closed form, f32x2-packed,
// polynomial sinpi/cospi (no MUFU in hot path), per-warp precompute (no block barrier).
// x: (32,224,224,1) f32, weights: (2,4,3) f32 -> out: (32,112,112,4) f32.

#define NB   32
#define IH   224
#define IW   224
#define OH   112
#define OW   112
#define NPATCH (NB * OH * OW)        // 401408
#define HALF   (NPATCH / 2)          // 200704
#define BOFF   (16 * IH * IW)        // element offset: batch + 16

#define THREADS 128
#define NWARPS  (THREADS / 32)
#define PI_F 3.14159265358979323846f

typedef unsigned long long f32x2;

__device__ __forceinline__ f32x2 pk(float lo, float hi) {
    f32x2 r; asm("mov.b64 %0, {%1, %2};" : "=l"(r) : "f"(lo), "f"(hi)); return r;
}
__device__ __forceinline__ void upk(f32x2 v, float& lo, float& hi) {
    asm("mov.b64 {%0, %1}, %2;" : "=f"(lo), "=f"(hi) : "l"(v));
}
__device__ __forceinline__ f32x2 fma2(f32x2 a, f32x2 b, f32x2 c) {
    f32x2 r; asm("fma.rn.f32x2 %0, %1, %2, %3;" : "=l"(r) : "l"(a), "l"(b), "l"(c)); return r;
}
__device__ __forceinline__ f32x2 mul2(f32x2 a, f32x2 b) {
    f32x2 r; asm("mul.rn.f32x2 %0, %1, %2;" : "=l"(r) : "l"(a), "l"(b)); return r;
}
__device__ __forceinline__ f32x2 add2(f32x2 a, f32x2 b) {
    f32x2 r; asm("add.rn.f32x2 %0, %1, %2;" : "=l"(r) : "l"(a), "l"(b)); return r;
}
__device__ __forceinline__ f32x2 dup(float v) { return pk(v, v); }

// Taylor coefficients (z = pi*u, series in v = u^2)
#define CC1 (-4.93480220054468f)
#define CC2 ( 4.05871212641677f)
#define CC3 (-1.33526276885459f)
#define CC4 ( 0.23533063035889f)
#define SS1 (-1.64493406684823f)
#define SS2 ( 0.81174242528335f)
#define SS3 (-0.19075182412038f)
#define SS4 ( 0.02614784782342f)

// per-warp shared coefficient layout (float2 entries, duplicated lanes):
//  [w*10 + i]  i<9 : Q[w] row-major, i=9 pad  -> ulonglong2 pairs w*5..w*5+4
//  [40..42] c0 ; [44..46] c1 ; [48..56] c2 ; [58..66] c3
__global__ __launch_bounds__(THREADS)
void qip_kernel(const float* __restrict__ x,
                const float* __restrict__ weights,
                float* __restrict__ out)
{
    __shared__ __align__(16) float2 sD[NWARPS][68];

    int t    = threadIdx.x;
    int wrp  = t >> 5;
    int lane = t & 31;

    int p0 = blockIdx.x * THREADS + t;   // 0 .. HALF-1
    int ow = p0 % OW;
    const float* base = x + (4 * p0 - 2 * ow);

    // issue all input loads before precompute (overlap latency)
    float2 r0a = *(const float2*)(base);
    float2 r1a = *(const float2*)(base + IW);
    float2 r0b = *(const float2*)(base + BOFF);
    float2 r1b = *(const float2*)(base + BOFF + IW);

    // -------- per-warp coefficient precompute (weights: use precise-enough MUFU) ----
    if (lane < 4) {
        const float* ww = weights + lane * 3;
        float sf, cf, st, ct, so, co;
        __sincosf(ww[0], &sf, &cf);
        __sincosf(ww[1], &st, &ct);
        __sincosf(ww[2], &so, &co);
        float M00 = ct * cf, M01 = -ct * sf, M02 = st;
        float M10 = sf,      M11 = cf;
        float M20 = -st * cf, M21 = st * sf, M22 = ct;
        float q[10];
        q[0] = co * M00 - so * M10; q[1] = -(co * M01 - so * M11); q[2] = co * M02;
        q[3] = so * M00 + co * M10; q[4] = -(so * M01 + co * M11); q[5] = so * M02;
        q[6] = M20;                 q[7] = -M21;                   q[8] = M22;
        q[9] = 0.f;
#pragma unroll
        for (int i = 0; i < 10; i++) sD[wrp][lane * 10 + i] = make_float2(q[i], q[i]);
    } else if (lane == 4 || lane == 5) {
        int wA = lane - 4;
        const float* wa = weights + 12 + wA * 3;
        const float* wb = weights + 12 + (wA + 2) * 3;
        float sfa, cfa, sta, cta, sfb, cfb, stb, ctb;
        __sincosf(wa[0], &sfa, &cfa);
        __sincosf(wa[1], &sta, &cta);
        __sincosf(wb[0], &sfb, &cfb);
        __sincosf(wb[1], &stb, &ctb);
        float ax = -sta * cfa, ay = sta * sfa, az = cta;
        float bx = -stb * cfb, by = stb * sfb, bz = ctb;
        if (lane == 4) {
            float c0v[4] = { bx, by, bz, 0.f };
#pragma unroll
            for (int i = 0; i < 4; i++) sD[wrp][40 + i] = make_float2(c0v[i], c0v[i]);
            float c2v[10] = { ax * bx, -ax * by, -ax * bz,
                             -ay * bx,  ay * by,  ay * bz,
                             -az * bx,  az * by,  az * bz, 0.f };
#pragma unroll
            for (int i = 0; i < 10; i++) sD[wrp][48 + i] = make_float2(c2v[i], c2v[i]);
        } else {
            float c1v[4] = { bx, -by, bz, 0.f };
#pragma unroll
            for (int i = 0; i < 4; i++) sD[wrp][44 + i] = make_float2(c1v[i], c1v[i]);
            float c3v[10] = { ax * bx, -ax * by, -ax * bz,
                              ay * bx,  ay * by,  ay * bz,
                             -az * bx,  az * by,  az * bz, 0.f };
#pragma unroll
            for (int i = 0; i < 10; i++) sD[wrp][58 + i] = make_float2(c3v[i], c3v[i]);
        }
    }
    __syncwarp();

    const ulonglong2* Dq = (const ulonglong2*)sD[wrp];

    float pa[4] = { r0a.x, r0a.y, r1a.x, r1a.y };
    float pb[4] = { r0b.x, r0b.y, r1b.x, r1b.y };

    // packed poly constants
    f32x2 Kh   = dup(-0.5f);
    f32x2 Knp  = dup(-PI_F);
    f32x2 Kc1 = dup(CC1), Kc2 = dup(CC2), Kc3 = dup(CC3), Kc4 = dup(CC4);
    f32x2 Ks1 = dup(SS1), Ks2 = dup(SS2), Ks3 = dup(SS3), Ks4 = dup(SS4);
    f32x2 Kone = dup(1.0f);

    f32x2 m0x, m0y, m0z, m1x, m1y, m1z, m2x, m2y, m2z, m3x, m3y, m3z;
#pragma unroll
    for (int w = 0; w < 4; w++) {
        // s = sin(pi x) = cos(pi u);  c = cos(pi x) = -sin(pi u), u = x-1/2
        f32x2 X = pk(pa[w], pb[w]);
        f32x2 u = add2(X, Kh);
        f32x2 v = mul2(u, u);
        f32x2 s = fma2(Kc4, v, Kc3);
        s = fma2(s, v, Kc2);
        s = fma2(s, v, Kc1);
        s = fma2(s, v, Kone);            // cos(pi u)
        f32x2 sp = fma2(Ks4, v, Ks3);
        sp = fma2(sp, v, Ks2);
        sp = fma2(sp, v, Ks1);
        sp = fma2(sp, v, Kone);
        f32x2 pu = mul2(u, Knp);         // -pi u
        f32x2 c = mul2(sp, pu);          // -sin(pi u) = cos(pi x)
        f32x2 t1 = s;
        f32x2 t0 = mul2(s, c);
        f32x2 t2 = mul2(c, c);

        ulonglong2 j0 = Dq[w * 5 + 0];
        ulonglong2 j1 = Dq[w * 5 + 1];
        ulonglong2 j2 = Dq[w * 5 + 2];
        ulonglong2 j3 = Dq[w * 5 + 3];
        ulonglong2 j4 = Dq[w * 5 + 4];
        f32x2 rx = fma2(j0.x, t0, fma2(j0.y, t1, mul2(j1.x, t2)));
        f32x2 ry = fma2(j1.y, t0, fma2(j2.x, t1, mul2(j2.y, t2)));
        f32x2 rz = fma2(j3.x, t0, fma2(j3.y, t1, mul2(j4.x, t2)));
        if (w == 0) { m0x = rx; m0y = ry; m0z = rz; }
        else if (w == 1) { m1x = rx; m1y = ry; m1z = rz; }
        else if (w == 2) { m2x = rx; m2y = ry; m2z = rz; }
        else { m3x = rx; m3y = ry; m3z = rz; }
    }

    f32x2 xx01 = mul2(m0x, m1x);
    f32x2 yy01 = mul2(m0y, m1y);
    f32x2 zz01 = mul2(m0z, m1z);
    f32x2 xy01 = mul2(m0x, m1y);
    f32x2 yx01 = mul2(m0y, m1x);
    f32x2 yz01 = mul2(m0y, m1z);
    f32x2 zy01 = mul2(m0z, m1y);
    f32x2 axx = mul2(m2x, m3x);
    f32x2 ayx = mul2(m2y, m3x);
    f32x2 ayy = mul2(m2y, m3y);
    f32x2 axy = mul2(m2x, m3y);
    f32x2 azy = mul2(m2z, m3y);
    f32x2 azz = mul2(m2z, m3z);
    f32x2 ayz = mul2(m2y, m3z);

    ulonglong2 p20 = Dq[20], p21 = Dq[21];
    f32x2 E0 = fma2(p20.x, axx,
               fma2(p20.y, mul2(zz01, ayx),
                    mul2(p21.x, mul2(zz01, m2z))));

    ulonglong2 p22 = Dq[22], p23 = Dq[23];
    f32x2 E1 = fma2(p22.x, mul2(xx01, m3x),
               fma2(p22.y, mul2(yy01, azy),
                    mul2(p23.x, mul2(zz01, azz))));

    ulonglong2 p24 = Dq[24], p25 = Dq[25], p26 = Dq[26], p27 = Dq[27], p28 = Dq[28];
    f32x2 E2 =      mul2(p24.x, mul2(xx01, axx));
    E2 = fma2(p24.y, mul2(yy01, ayx), E2);
    E2 = fma2(p25.x, mul2(yy01, m2z), E2);
    E2 = fma2(p25.y, mul2(xy01, ayy), E2);
    E2 = fma2(p26.x, mul2(yx01, axy), E2);
    E2 = fma2(p26.y, mul2(yx01, m3z), E2);
    E2 = fma2(p27.x, mul2(m1z, ayy), E2);
    E2 = fma2(p27.y, mul2(m0z, axy), E2);
    E2 = fma2(p28.x, mul2(m0z, m3z), E2);

    ulonglong2 p29 = Dq[29], p30 = Dq[30], p31 = Dq[31], p32 = Dq[32], p33 = Dq[33];
    f32x2 E3 =      mul2(p29.x, mul2(m0x, axx));
    E3 = fma2(p29.y, mul2(yz01, ayy), E3);
    E3 = fma2(p30.x, mul2(zy01, ayz), E3);
    E3 = fma2(p30.y, mul2(yz01, axx), E3);
    E3 = fma2(p31.x, mul2(m0x, ayy), E3);
    E3 = fma2(p31.y, mul2(m1x, ayz), E3);
    E3 = fma2(p32.x, mul2(yy01, m3x), E3);
    E3 = fma2(p32.y, mul2(xx01, azy), E3);
    E3 = fma2(p33.x, azz, E3);

    float e0a, e0b, e1a, e1b, e2a, e2b, e3a, e3b;
    upk(E0, e0a, e0b);
    upk(E1, e1a, e1b);
    upk(E2, e2a, e2b);
    upk(E3, e3a, e3b);

    float4* o = (float4*)out;
    o[p0]        = make_float4(e0a, e1a, e2a, e3a);
    o[p0 + HALF] = make_float4(e0b, e1b, e2b, e3b);
}

extern "C" void kernel_launch(void* const* d_in, const int* in_sizes, int n_in,
                              void* d_out, int out_size) {
    const float* x = (const float*)d_in[0];
    const float* w = (const float*)d_in[1];
    float* out = (float*)d_out;
    qip_kernel<<<HALF / THREADS, THREADS>>>(x, w, out);
}

// round 9
// speedup vs baseline: 1.2129x; 1.2129x over previous
#include <cuda_runtime.h>

// QuantumImagePreprocessor: Heisenberg closed form, f32x2-packed over 2 ow-adjacent
// patches (same image) -> 2 LDG.128 + 2 STG.128 per thread.
// x: (32,224,224,1) f32, weights: (2,4,3) f32 -> out: (32,112,112,4) f32.

#define NB   32
#define IH   224
#define IW   224
#define OH   112
#define OW   112
#define NPATCH (NB * OH * OW)        // 401408
#define NPAIR  (NPATCH / 2)          // 200704 ow-adjacent pairs
#define QW     (OW / 2)              // 56

#define THREADS 128
#define PI_F 3.14159265358979323846f

typedef unsigned long long f32x2;

__device__ __forceinline__ f32x2 pk(float lo, float hi) {
    f32x2 r; asm("mov.b64 %0, {%1, %2};" : "=l"(r) : "f"(lo), "f"(hi)); return r;
}
__device__ __forceinline__ void upk(f32x2 v, float& lo, float& hi) {
    asm("mov.b64 {%0, %1}, %2;" : "=f"(lo), "=f"(hi) : "l"(v));
}
__device__ __forceinline__ f32x2 fma2(f32x2 a, f32x2 b, f32x2 c) {
    f32x2 r; asm("fma.rn.f32x2 %0, %1, %2, %3;" : "=l"(r) : "l"(a), "l"(b), "l"(c)); return r;
}
__device__ __forceinline__ f32x2 mul2(f32x2 a, f32x2 b) {
    f32x2 r; asm("mul.rn.f32x2 %0, %1, %2;" : "=l"(r) : "l"(a), "l"(b)); return r;
}

// shared coefficient layout (float2 entries, value duplicated in both lanes):
//  [w*10 + i]  i<9 : Q[w] row-major, i=9 pad  -> ulonglong2 pairs w*5 .. w*5+4
//  [40..42] c0 ; [44..46] c1 ; [48..56] c2 ; [58..66] c3
__global__ __launch_bounds__(THREADS)
void qip_kernel(const float* __restrict__ x,
                const float* __restrict__ weights,
                float* __restrict__ out)
{
    __shared__ __align__(16) float2 sD[68];

    int t = threadIdx.x;
    if (t < 4) {
        const float* ww = weights + t * 3;
        float sf, cf, st, ct, so, co;
        __sincosf(ww[0], &sf, &cf);
        __sincosf(ww[1], &st, &ct);
        __sincosf(ww[2], &so, &co);
        float M00 = ct * cf, M01 = -ct * sf, M02 = st;
        float M10 = sf,      M11 = cf;
        float M20 = -st * cf, M21 = st * sf, M22 = ct;
        float q[10];
        q[0] = co * M00 - so * M10; q[1] = -(co * M01 - so * M11); q[2] = co * M02;
        q[3] = so * M00 + co * M10; q[4] = -(so * M01 + co * M11); q[5] = so * M02;
        q[6] = M20;                 q[7] = -M21;                   q[8] = M22;
        q[9] = 0.f;
#pragma unroll
        for (int i = 0; i < 10; i++) sD[t * 10 + i] = make_float2(q[i], q[i]);
    } else if (t == 4 || t == 5) {
        int wA = t - 4;
        const float* wa = weights + 12 + wA * 3;
        const float* wb = weights + 12 + (wA + 2) * 3;
        float sfa, cfa, sta, cta, sfb, cfb, stb, ctb;
        __sincosf(wa[0], &sfa, &cfa);
        __sincosf(wa[1], &sta, &cta);
        __sincosf(wb[0], &sfb, &cfb);
        __sincosf(wb[1], &stb, &ctb);
        float ax = -sta * cfa, ay = sta * sfa, az = cta;
        float bx = -stb * cfb, by = stb * sfb, bz = ctb;
        if (t == 4) {
            float c0v[4] = { bx, by, bz, 0.f };
#pragma unroll
            for (int i = 0; i < 4; i++) sD[40 + i] = make_float2(c0v[i], c0v[i]);
            float c2v[10] = { ax * bx, -ax * by, -ax * bz,
                             -ay * bx,  ay * by,  ay * bz,
                             -az * bx,  az * by,  az * bz, 0.f };
#pragma unroll
            for (int i = 0; i < 10; i++) sD[48 + i] = make_float2(c2v[i], c2v[i]);
        } else {
            float c1v[4] = { bx, -by, bz, 0.f };
#pragma unroll
            for (int i = 0; i < 4; i++) sD[44 + i] = make_float2(c1v[i], c1v[i]);
            float c3v[10] = { ax * bx, -ax * by, -ax * bz,
                              ay * bx,  ay * by,  ay * bz,
                             -az * bx,  az * by,  az * bz, 0.f };
#pragma unroll
            for (int i = 0; i < 10; i++) sD[58 + i] = make_float2(c3v[i], c3v[i]);
        }
    }
    __syncthreads();

    const ulonglong2* Dq = (const ulonglong2*)sD;

    int P = blockIdx.x * THREADS + t;    // pair index 0 .. NPAIR-1
    int q = P % QW;                      // ow-pair within row
    // input element offset of (b, 2oh, 4q): 8P - 4q   [P=(b*OH+oh)*QW+q]
    const float* base = x + (8 * P - 4 * q);

    float4 r0 = *(const float4*)(base);        // row 2oh : pixels for patches j=0,1
    float4 r1 = *(const float4*)(base + IW);   // row 2oh+1

    // lane lo = patch j=0 (cols 4q,4q+1), lane hi = patch j=1 (cols 4q+2,4q+3)
    // wires: 0 = r0 even col, 1 = r0 odd col, 2 = r1 even col, 3 = r1 odd col
    float pa[4] = { r0.x, r0.y, r1.x, r1.y };   // lane lo
    float pb[4] = { r0.z, r0.w, r1.z, r1.w };   // lane hi

    f32x2 m0x, m0y, m0z, m1x, m1y, m1z, m2x, m2y, m2z, m3x, m3y, m3z;
#pragma unroll
    for (int w = 0; w < 4; w++) {
        float sA, cA, sB, cB;
        __sincosf(pa[w] * PI_F, &sA, &cA);
        __sincosf(pb[w] * PI_F, &sB, &cB);
        f32x2 t1 = pk(sA, sB);        // s
        f32x2 tc = pk(cA, cB);        // c
        f32x2 t0 = mul2(t1, tc);      // s*c
        f32x2 t2 = mul2(tc, tc);      // c*c
        ulonglong2 j0 = Dq[w * 5 + 0];
        ulonglong2 j1 = Dq[w * 5 + 1];
        ulonglong2 j2 = Dq[w * 5 + 2];
        ulonglong2 j3 = Dq[w * 5 + 3];
        ulonglong2 j4 = Dq[w * 5 + 4];
        f32x2 rx = fma2(j0.x, t0, fma2(j0.y, t1, mul2(j1.x, t2)));
        f32x2 ry = fma2(j1.y, t0, fma2(j2.x, t1, mul2(j2.y, t2)));
        f32x2 rz = fma2(j3.x, t0, fma2(j3.y, t1, mul2(j4.x, t2)));
        if (w == 0) { m0x = rx; m0y = ry; m0z = rz; }
        else if (w == 1) { m1x = rx; m1y = ry; m1z = rz; }
        else if (w == 2) { m2x = rx; m2y = ry; m2z = rz; }
        else { m3x = rx; m3y = ry; m3z = rz; }
    }

    f32x2 xx01 = mul2(m0x, m1x);
    f32x2 yy01 = mul2(m0y, m1y);
    f32x2 zz01 = mul2(m0z, m1z);
    f32x2 xy01 = mul2(m0x, m1y);
    f32x2 yx01 = mul2(m0y, m1x);
    f32x2 yz01 = mul2(m0y, m1z);
    f32x2 zy01 = mul2(m0z, m1y);
    f32x2 axx = mul2(m2x, m3x);
    f32x2 ayx = mul2(m2y, m3x);
    f32x2 ayy = mul2(m2y, m3y);
    f32x2 axy = mul2(m2x, m3y);
    f32x2 azy = mul2(m2z, m3y);
    f32x2 azz = mul2(m2z, m3z);
    f32x2 ayz = mul2(m2y, m3z);

    ulonglong2 p20 = Dq[20], p21 = Dq[21];
    f32x2 E0 = fma2(p20.x, axx,
               fma2(p20.y, mul2(zz01, ayx),
                    mul2(p21.x, mul2(zz01, m2z))));

    ulonglong2 p22 = Dq[22], p23 = Dq[23];
    f32x2 E1 = fma2(p22.x, mul2(xx01, m3x),
               fma2(p22.y, mul2(yy01, azy),
                    mul2(p23.x, mul2(zz01, azz))));

    ulonglong2 p24 = Dq[24], p25 = Dq[25], p26 = Dq[26], p27 = Dq[27], p28 = Dq[28];
    f32x2 E2 =      mul2(p24.x, mul2(xx01, axx));
    E2 = fma2(p24.y, mul2(yy01, ayx), E2);
    E2 = fma2(p25.x, mul2(yy01, m2z), E2);
    E2 = fma2(p25.y, mul2(xy01, ayy), E2);
    E2 = fma2(p26.x, mul2(yx01, axy), E2);
    E2 = fma2(p26.y, mul2(yx01, m3z), E2);
    E2 = fma2(p27.x, mul2(m1z, ayy), E2);
    E2 = fma2(p27.y, mul2(m0z, axy), E2);
    E2 = fma2(p28.x, mul2(m0z, m3z), E2);

    ulonglong2 p29 = Dq[29], p30 = Dq[30], p31 = Dq[31], p32 = Dq[32], p33 = Dq[33];
    f32x2 E3 =      mul2(p29.x, mul2(m0x, axx));
    E3 = fma2(p29.y, mul2(yz01, ayy), E3);
    E3 = fma2(p30.x, mul2(zy01, ayz), E3);
    E3 = fma2(p30.y, mul2(yz01, axx), E3);
    E3 = fma2(p31.x, mul2(m0x, ayy), E3);
    E3 = fma2(p31.y, mul2(m1x, ayz), E3);
    E3 = fma2(p32.x, mul2(yy01, m3x), E3);
    E3 = fma2(p32.y, mul2(xx01, azy), E3);
    E3 = fma2(p33.x, azz, E3);

    float e0a, e0b, e1a, e1b, e2a, e2b, e3a, e3b;
    upk(E0, e0a, e0b);
    upk(E1, e1a, e1b);
    upk(E2, e2a, e2b);
    upk(E3, e3a, e3b);

    // output patch indices 2P (lane lo) and 2P+1 (lane hi): contiguous float4 pair
    float4* o = (float4*)out;
    o[2 * P]     = make_float4(e0a, e1a, e2a, e3a);
    o[2 * P + 1] = make_float4(e0b, e1b, e2b, e3b);
}

extern "C" void kernel_launch(void* const* d_in, const int* in_sizes, int n_in,
                              void* d_out, int out_size) {
    const float* x = (const float*)d_in[0];
    const float* w = (const float*)d_in[1];
    float* out = (float*)d_out;
    qip_kernel<<<NPAIR / THREADS, THREADS>>>(x, w, out);
}